// round 13
// baseline (speedup 1.0000x reference)
#include <cuda_runtime.h>
#include <cuda_fp16.h>

// Problem constants (fixed shapes for this problem)
#define Nn    50000
#define FIN   128
#define D1    128           // H1*C1
#define NC    16
#define EMAX  1600000
#define ETMAX (EMAX + Nn)

// ---------------- scratch (device globals; no allocation allowed) ------------
__device__ unsigned   g_w1f[8 * 16 * 32 * 2]; // w1 in mma B-fragment order (half2 as u32)
__device__ float4     g_w2t4[(D1 / 4) * NC];
__device__ __half2    g_xw1h[Nn * 64];        // fp16 gather payload (layer 1)
__device__ __half2    g_out1h[Nn * 64];       // fp16 layer-1 output
__device__ float      g_asrc1[Nn * 2];
__device__ float      g_adst1[Nn * 2];
__device__ __half     g_xw2h[Nn * NC];        // fp16 gather payload (layer 2)
__device__ float      g_asrc2[Nn];
__device__ float      g_adst2[Nn];
__device__ unsigned   g_cnt[Nn];              // invariant: zero at kernel_launch entry
__device__ unsigned   g_off[Nn + 1];
__device__ unsigned   g_cur[Nn];
__device__ int        g_adj[ETMAX];           // CSR by dst: src node ids

__device__ __forceinline__ float lrelu(float a) { return a > 0.f ? a : 0.2f * a; }

// ---------------- prep: w1 -> B-fragment repack, w2 repack -------------------
__global__ void k_prep(const float* __restrict__ w1, const float* __restrict__ w2) {
    int i = blockIdx.x * blockDim.x + threadIdx.x;
    if (i < 8 * 16 * 32 * 2) {
        int reg  = i & 1;
        int lane = (i >> 1) & 31;
        int nfg  = (i >> 6) & 15;
        int ks   = i >> 10;
        int nn = nfg * 8 + (lane >> 2);                 // output channel
        int k  = ks * 16 + (lane & 3) * 2 + reg * 8;    // input channel
        __half2 h = __floats2half2_rn(w1[nn * FIN + k], w1[nn * FIN + k + 1]);
        g_w1f[i] = *(unsigned*)&h;
    }
    if (i < NC * D1) {
        int o = i / D1, k = i % D1;                     // w2: [NC][D1]
        ((float*)g_w2t4)[((k >> 2) * NC + o) * 4 + (k & 3)] = w2[i];
    }
}

// ---------------- CSR build (int4-vectorized) --------------------------------
__global__ void k_hist(const int* __restrict__ ei, int E, int ET) {
    int i = blockIdx.x * blockDim.x + threadIdx.x;
    int base = i * 4;
    if (base < E) {                         // E % 4 == 0, so no straddle
        int4 d4 = *(const int4*)&ei[E + base];
        atomicAdd(&g_cnt[d4.x], 1u);
        atomicAdd(&g_cnt[d4.y], 1u);
        atomicAdd(&g_cnt[d4.z], 1u);
        atomicAdd(&g_cnt[d4.w], 1u);
    } else {
#pragma unroll
        for (int r = 0; r < 4; r++) {
            int e = base + r;
            if (e < ET) atomicAdd(&g_cnt[e - E], 1u);
        }
    }
}

__global__ void k_scan(int n) {
    __shared__ unsigned ssum[1024];
    int t = threadIdx.x;
    int chunk = (n + 1023) >> 10;
    int b = t * chunk;
    int e = min(b + chunk, n);
    unsigned sum = 0;
    for (int i = b; i < e; i++) sum += g_cnt[i];
    ssum[t] = sum;
    __syncthreads();
    for (int o = 1; o < 1024; o <<= 1) {
        unsigned v = (t >= o) ? ssum[t - o] : 0u;
        __syncthreads();
        ssum[t] += v;
        __syncthreads();
    }
    unsigned run = (t == 0) ? 0u : ssum[t - 1];
    for (int i = b; i < e; i++) {
        unsigned c = g_cnt[i];
        g_cnt[i] = 0u;                            // restore invariant
        g_off[i] = run;
        g_cur[i] = run;
        run += c;
    }
    if (t == 0) g_off[n] = ssum[1023];
}

__global__ void k_scatter(const int* __restrict__ ei, int E, int ET) {
    int i = blockIdx.x * blockDim.x + threadIdx.x;
    int base = i * 4;
    if (base < E) {
        int4 s4 = *(const int4*)&ei[base];
        int4 d4 = *(const int4*)&ei[E + base];
        g_adj[atomicAdd(&g_cur[d4.x], 1u)] = s4.x;
        g_adj[atomicAdd(&g_cur[d4.y], 1u)] = s4.y;
        g_adj[atomicAdd(&g_cur[d4.z], 1u)] = s4.z;
        g_adj[atomicAdd(&g_cur[d4.w], 1u)] = s4.w;
    } else {
#pragma unroll
        for (int r = 0; r < 4; r++) {
            int e = base + r;
            if (e < ET) {
                int sl = e - E;
                g_adj[atomicAdd(&g_cur[sl], 1u)] = sl;
            }
        }
    }
}

// ------- layer-1 GEMM via fp16 HMMA (x converted inline) + att1 + payload ----
// 64 nodes/block; 8 warps = 4 M-frags x 2 N-halves; N-half == attention head.
__global__ __launch_bounds__(256) void k_gemm1(const float* __restrict__ x,
                                               const float* __restrict__ att_s,
                                               const float* __restrict__ att_d, int n) {
    int tid = threadIdx.x;
    int w = tid >> 5, t = tid & 31;
    int mfrag = w >> 1, nhalf = w & 1;
    int r = t >> 2, q = t & 3;
    int node0 = blockIdx.x * 64 + mfrag * 16 + r;
    int node1 = node0 + 8;
    int nl0 = min(node0, n - 1) * FIN;
    int nl1 = min(node1, n - 1) * FIN;

    float c[8][4];
#pragma unroll
    for (int nf = 0; nf < 8; nf++)
#pragma unroll
        for (int j = 0; j < 4; j++) c[nf][j] = 0.f;

#pragma unroll
    for (int ks = 0; ks < 8; ks++) {
        int kb = ks * 16 + q * 2;
        float2 xa0 = *(const float2*)&x[nl0 + kb];
        float2 xa1 = *(const float2*)&x[nl1 + kb];
        float2 xa2 = *(const float2*)&x[nl0 + kb + 8];
        float2 xa3 = *(const float2*)&x[nl1 + kb + 8];
        __half2 h0 = __floats2half2_rn(xa0.x, xa0.y);
        __half2 h1 = __floats2half2_rn(xa1.x, xa1.y);
        __half2 h2 = __floats2half2_rn(xa2.x, xa2.y);
        __half2 h3 = __floats2half2_rn(xa3.x, xa3.y);
        unsigned a0 = *(unsigned*)&h0, a1 = *(unsigned*)&h1;
        unsigned a2 = *(unsigned*)&h2, a3 = *(unsigned*)&h3;
#pragma unroll
        for (int nf = 0; nf < 8; nf++) {
            int nfg = nhalf * 8 + nf;
            uint2 b = *(const uint2*)&g_w1f[((ks * 16 + nfg) * 32 + t) * 2];
            asm volatile(
                "mma.sync.aligned.m16n8k16.row.col.f32.f16.f16.f32 "
                "{%0,%1,%2,%3}, {%4,%5,%6,%7}, {%8,%9}, {%0,%1,%2,%3};\n"
                : "+f"(c[nf][0]), "+f"(c[nf][1]), "+f"(c[nf][2]), "+f"(c[nf][3])
                : "r"(a0), "r"(a1), "r"(a2), "r"(a3), "r"(b.x), "r"(b.y));
        }
    }

    // epilogue: payload stores + per-head attention dots (head == nhalf)
    float ps0 = 0.f, pd0 = 0.f, ps1 = 0.f, pd1 = 0.f;
#pragma unroll
    for (int nf = 0; nf < 8; nf++) {
        int col = nhalf * 64 + nf * 8 + q * 2;
        float as0 = att_s[col], as1 = att_s[col + 1];
        float ad0 = att_d[col], ad1 = att_d[col + 1];
        ps0 += c[nf][0] * as0 + c[nf][1] * as1;
        pd0 += c[nf][0] * ad0 + c[nf][1] * ad1;
        ps1 += c[nf][2] * as0 + c[nf][3] * as1;
        pd1 += c[nf][2] * ad0 + c[nf][3] * ad1;
        int pidx = nhalf * 32 + nf * 4 + q;
        if (node0 < n) g_xw1h[node0 * 64 + pidx] = __floats2half2_rn(c[nf][0], c[nf][1]);
        if (node1 < n) g_xw1h[node1 * 64 + pidx] = __floats2half2_rn(c[nf][2], c[nf][3]);
    }
#pragma unroll
    for (int o = 1; o <= 2; o <<= 1) {
        ps0 += __shfl_xor_sync(0xffffffffu, ps0, o);
        pd0 += __shfl_xor_sync(0xffffffffu, pd0, o);
        ps1 += __shfl_xor_sync(0xffffffffu, ps1, o);
        pd1 += __shfl_xor_sync(0xffffffffu, pd1, o);
    }
    if (q == 0) {
        if (node0 < n) { g_asrc1[node0 * 2 + nhalf] = ps0; g_adst1[node0 * 2 + nhalf] = pd0; }
        if (node1 < n) { g_asrc1[node1 * 2 + nhalf] = ps1; g_adst1[node1 * 2 + nhalf] = pd1; }
    }
}

// ------- layer-1 softmax+aggregate: warp/dst, packed single-shfl + hfma2 -----
// pk = {src:16, half(ex):16}; lanes 0-15 carry head0's ex, 16-31 head1's.
__global__ void k_edge1(const float* __restrict__ b1, int n) {
    int gt = blockIdx.x * blockDim.x + threadIdx.x;
    int d  = gt >> 5;
    if (d >= n) return;
    int lane = gt & 31, h = lane >> 4, sub = lane & 15;
    int beg = (int)g_off[d], end = (int)g_off[d + 1];
    float adh = g_adst1[d * 2 + h];
    float2 f01 = make_float2(0.f, 0.f), f23 = make_float2(0.f, 0.f);
    float s = 0.f;
    int base = beg;
    unsigned pk = 0u; float ex = 0.f;
    {
        int i0 = base + sub;
        if (i0 < end) {
            int msrc = g_adj[i0];
            ex = __expf(lrelu(g_asrc1[msrc * 2 + h] + adh));
            __half eh = __float2half(ex);
            pk = (unsigned)msrc | ((unsigned)*(unsigned short*)&eh << 16);
        }
    }
    while (base < end) {
        int nbase = base + 16;
        unsigned npk = 0u; float nex = 0.f;
        if (nbase < end) {              // software-pipeline next chunk's dep chain
            int i1 = nbase + sub;
            if (i1 < end) {
                int nsrc = g_adj[i1];
                nex = __expf(lrelu(g_asrc1[nsrc * 2 + h] + adh));
                __half eh = __float2half(nex);
                npk = (unsigned)nsrc | ((unsigned)*(unsigned short*)&eh << 16);
            }
        }
        s += ex;
        int cnt = min(16, end - base);
        __half2 ha = __float2half2_rn(0.f), hb = ha;
#pragma unroll 8
        for (int j = 0; j < cnt; j++) {
            unsigned v = __shfl_sync(0xffffffffu, pk, j + (h << 4));
            unsigned cc;
            asm("prmt.b32 %0, %1, %1, 0x3232;" : "=r"(cc) : "r"(v));  // half2(c,c)
            uint2 p = *(const uint2*)&g_xw1h[(v & 0xFFFFu) * 64 + lane * 2];
            ha = __hfma2(*(__half2*)&p.x, *(__half2*)&cc, ha);
            hb = __hfma2(*(__half2*)&p.y, *(__half2*)&cc, hb);
        }
        float2 fa = __half22float2(ha), fb = __half22float2(hb);
        f01.x += fa.x; f01.y += fa.y; f23.x += fb.x; f23.y += fb.y;
        pk = npk; ex = nex; base = nbase;
    }
#pragma unroll
    for (int o = 8; o >= 1; o >>= 1)    // per-half sums: lanes<16 -> s0, >=16 -> s1
        s += __shfl_xor_sync(0xffffffffu, s, o);
    float r = 1.f / (s + 1e-16f);
    float4 bb = *(const float4*)&b1[lane * 4];
    __half2 o01 = __floats2half2_rn(f01.x * r + bb.x, f01.y * r + bb.y);
    __half2 o23 = __floats2half2_rn(f23.x * r + bb.z, f23.y * r + bb.w);
    uint2 pko = make_uint2(*(unsigned*)&o01, *(unsigned*)&o23);
    *(uint2*)&g_out1h[d * 64 + lane * 2] = pko;
}

// ----- layer-2 GEMM (16 nodes/block, fp16 in + relu fused) + att2 dots -------
__global__ __launch_bounds__(256) void k_gemm2(const float* __restrict__ att_s,
                                               const float* __restrict__ att_d, int n) {
    __shared__ float xs[16 * 132];
    int t  = threadIdx.x;            // 256 threads = 16 nodes x 16 outs
    int nb = blockIdx.x * 16;
#pragma unroll
    for (int i = 0; i < 4; i++) {
        int idx  = t + i * 256;      // 0..1023 over 16 nodes x 64 half2
        int node = idx >> 6, kh = idx & 63;
        float2 v = make_float2(0.f, 0.f);
        if (nb + node < n) {
            __half2 hv = g_out1h[(nb + node) * 64 + kh];
            v = __half22float2(hv);
        }
        xs[node * 132 + kh * 2 + 0] = fmaxf(v.x, 0.f);   // relu
        xs[node * 132 + kh * 2 + 1] = fmaxf(v.y, 0.f);
    }
    __syncthreads();
    int ni = t >> 4;
    int o  = t & 15;
    float a0 = 0.f, a1 = 0.f, a2 = 0.f, a3 = 0.f;
#pragma unroll
    for (int k4 = 0; k4 < D1 / 4; k4 += 4) {
#pragma unroll
        for (int u = 0; u < 4; u++) {
            float4 w  = g_w2t4[(k4 + u) * NC + o];
            float4 xv = *(const float4*)&xs[ni * 132 + (k4 + u) * 4];
            float p = xv.x * w.x + xv.y * w.y + xv.z * w.z + xv.w * w.w;
            if (u == 0) a0 += p; else if (u == 1) a1 += p; else if (u == 2) a2 += p; else a3 += p;
        }
    }
    float acc = (a0 + a1) + (a2 + a3);
    int node = nb + ni;
    if (node < n) g_xw2h[node * NC + o] = __float2half(acc);
    float ps = acc * att_s[o];
    float pd = acc * att_d[o];
#pragma unroll
    for (int j = 8; j >= 1; j >>= 1) {
        ps += __shfl_xor_sync(0xffffffffu, ps, j);
        pd += __shfl_xor_sync(0xffffffffu, pd, j);
    }
    if (o == 0 && node < n) { g_asrc2[node] = ps; g_adst2[node] = pd; }
}

// ---------------- layer-2 fused softmax+aggregate (warp per dst) -------------
__global__ void k_edge2(const float* __restrict__ b2, float* __restrict__ out, int n) {
    int gt = blockIdx.x * blockDim.x + threadIdx.x;
    int d  = gt >> 5;
    if (d >= n) return;
    int lane = gt & 31;
    int beg = (int)g_off[d], end = (int)g_off[d + 1];
    float add = g_adst2[d];
    int half = lane >> 4;
    int c    = lane & 15;
    float acc = 0.f, s = 0.f;
    for (int base = beg; base < end; base += 32) {
        int myi = base + lane;
        float ev = 0.f;
        int msrc = 0;
        if (myi < end) {
            msrc = g_adj[myi];
            ev = __expf(lrelu(g_asrc2[msrc] + add));
        }
        s += ev;
        int cnt = min(32, end - base);
#pragma unroll 4
        for (int j = 0; j < cnt; j += 2) {
            int jj = j + half;                  // lanes 0-15 edge j, 16-31 edge j+1
            int   src = __shfl_sync(0xffffffffu, msrc, jj & 31);
            float e   = __shfl_sync(0xffffffffu, ev, jj & 31);
            if (jj < cnt)
                acc += __half2float(g_xw2h[src * NC + c]) * e;
        }
    }
#pragma unroll
    for (int o = 16; o >= 1; o >>= 1)
        s += __shfl_xor_sync(0xffffffffu, s, o);
    acc += __shfl_xor_sync(0xffffffffu, acc, 16);
    if (half == 0) {
        float r = 1.f / (s + 1e-16f);
        out[d * NC + c] = acc * r + b2[c];
    }
}

// ---------------- launcher ----------------------------------------------------
extern "C" void kernel_launch(void* const* d_in, const int* in_sizes, int n_in,
                              void* d_out, int out_size) {
    const float* x   = (const float*)d_in[0];
    const int*   ei  = (const int*)d_in[1];      // int32
    const float* w1  = (const float*)d_in[2];
    const float* as1 = (const float*)d_in[3];
    const float* ad1 = (const float*)d_in[4];
    const float* b1  = (const float*)d_in[5];
    const float* w2  = (const float*)d_in[6];
    const float* as2 = (const float*)d_in[7];
    const float* ad2 = (const float*)d_in[8];
    const float* b2  = (const float*)d_in[9];
    float* out = (float*)d_out;

    int n  = in_sizes[0] / FIN;     // 50000
    int E  = in_sizes[1] / 2;       // 1600000
    int ET = E + n;                 // 1650000
    int q4 = (ET + 3) / 4;          // int4-vectorized edge threads

    // 0: weight repacks
    k_prep<<<(8 * 16 * 32 * 2 + 255) / 256, 256>>>(w1, w2);
    // 1: CSR histogram (int4)
    k_hist<<<(q4 + 255) / 256, 256>>>(ei, E, ET);
    // 2: CSR scan
    k_scan<<<1, 1024>>>(n);
    // 3 (profiled): tensor-core GEMM1 + att1 dots + payload
    k_gemm1<<<(n + 63) / 64, 256>>>(x, as1, ad1, n);
    // CSR scatter (int4)
    k_scatter<<<(q4 + 255) / 256, 256>>>(ei, E, ET);
    // layer-1 softmax+aggregate (packed shfl + hfma2)
    k_edge1<<<(n * 32 + 255) / 256, 256>>>(b1, n);
    // layer 2
    k_gemm2<<<(n + 15) / 16, 256>>>(as2, ad2, n);
    k_edge2<<<(n * 32 + 255) / 256, 256>>>(b2, out, n);
}

// round 14
// speedup vs baseline: 1.0344x; 1.0344x over previous
#include <cuda_runtime.h>
#include <cuda_fp16.h>

// Problem constants (fixed shapes for this problem)
#define Nn    50000
#define FIN   128
#define D1    128           // H1*C1
#define NC    16
#define EMAX  1600000
#define ETMAX (EMAX + Nn)

// ---------------- scratch (device globals; no allocation allowed) ------------
__device__ unsigned   g_w1f[8 * 16 * 32 * 2]; // w1 in mma B-fragment order (half2 as u32)
__device__ float4     g_w2t4[(D1 / 4) * NC];
__device__ __half2    g_xw1h[Nn * 64];        // fp16 gather payload (layer 1)
__device__ __half2    g_out1h[Nn * 64];       // fp16 layer-1 output
__device__ float      g_asrc1[Nn * 2];
__device__ float      g_adst1[Nn * 2];
__device__ __half     g_xw2h[Nn * NC];        // fp16 gather payload (layer 2)
__device__ float      g_asrc2[Nn];
__device__ float      g_adst2[Nn];
__device__ unsigned   g_cnt[Nn];              // invariant: zero at kernel_launch entry
__device__ unsigned   g_off[Nn + 1];
__device__ unsigned   g_cur[Nn];
__device__ int        g_adj[ETMAX];           // CSR by dst: src node ids
__device__ unsigned   g_tick;                 // invariant: zero at kernel_launch entry

__device__ __forceinline__ float lrelu(float a) { return a > 0.f ? a : 0.2f * a; }

// ------ K1: prep (weight repack) + CSR histogram + last-block scan -----------
__global__ __launch_bounds__(1024) void k_build(const float* __restrict__ w1,
                                                const float* __restrict__ w2,
                                                const int* __restrict__ ei,
                                                int E, int ET, int n) {
    int gi = blockIdx.x * 1024 + threadIdx.x;
    // prep: w1 -> mma B-fragment order
    if (gi < 8 * 16 * 32 * 2) {
        int reg  = gi & 1;
        int lane = (gi >> 1) & 31;
        int nfg  = (gi >> 6) & 15;
        int ks   = gi >> 10;
        int nn = nfg * 8 + (lane >> 2);
        int k  = ks * 16 + (lane & 3) * 2 + reg * 8;
        __half2 h = __floats2half2_rn(w1[nn * FIN + k], w1[nn * FIN + k + 1]);
        g_w1f[gi] = *(unsigned*)&h;
    }
    if (gi < NC * D1) {
        int o = gi / D1, k = gi % D1;
        ((float*)g_w2t4)[((k >> 2) * NC + o) * 4 + (k & 3)] = w2[gi];
    }
    // histogram
    if (gi < ET) {
        int d = (gi < E) ? ei[E + gi] : (gi - E);
        atomicAdd(&g_cnt[d], 1u);
    }
    // ticket: last block performs the scan
    __threadfence();
    __syncthreads();
    __shared__ unsigned s_last;
    if (threadIdx.x == 0)
        s_last = (atomicAdd(&g_tick, 1u) == gridDim.x - 1) ? 1u : 0u;
    __syncthreads();
    if (!s_last) return;

    // 1024-thread scan over g_cnt (+ re-zero), producing g_off / g_cur
    __shared__ unsigned ssum[1024];
    int t = threadIdx.x;
    int chunk = (n + 1023) >> 10;
    int b = t * chunk;
    int e = min(b + chunk, n);
    unsigned sum = 0;
    for (int i = b; i < e; i++) sum += g_cnt[i];
    ssum[t] = sum;
    __syncthreads();
    for (int o = 1; o < 1024; o <<= 1) {
        unsigned v = (t >= o) ? ssum[t - o] : 0u;
        __syncthreads();
        ssum[t] += v;
        __syncthreads();
    }
    unsigned run = (t == 0) ? 0u : ssum[t - 1];
    for (int i = b; i < e; i++) {
        unsigned c = g_cnt[i];
        g_cnt[i] = 0u;                            // restore invariant
        g_off[i] = run;
        g_cur[i] = run;
        run += c;
    }
    if (t == 0) { g_off[n] = ssum[1023]; g_tick = 0u; }   // restore invariant
}

// ------ K2: gemm1 (blocks [0,g1)) + CSR scatter (blocks [g1,...)) ------------
// gemm1: 64 nodes/block; 8 warps = 4 M-frags x 2 N-halves; N-half == head.
__global__ __launch_bounds__(256) void k_g1scatter(const float* __restrict__ x,
                                                   const int* __restrict__ ei,
                                                   const float* __restrict__ att_s,
                                                   const float* __restrict__ att_d,
                                                   int n, int E, int ET, int g1) {
    if (blockIdx.x >= g1) {
        // ---- scatter path ----
        int e = (blockIdx.x - g1) * 256 + threadIdx.x;
        if (e >= ET) return;
        int s, d;
        if (e < E) { s = ei[e]; d = ei[E + e]; } else { s = d = e - E; }
        unsigned pos = atomicAdd(&g_cur[d], 1u);
        g_adj[pos] = s;
        return;
    }
    // ---- gemm1 path ----
    int tid = threadIdx.x;
    int w = tid >> 5, t = tid & 31;
    int mfrag = w >> 1, nhalf = w & 1;
    int r = t >> 2, q = t & 3;
    int node0 = blockIdx.x * 64 + mfrag * 16 + r;
    int node1 = node0 + 8;
    int nl0 = min(node0, n - 1) * FIN;
    int nl1 = min(node1, n - 1) * FIN;

    float c[8][4];
#pragma unroll
    for (int nf = 0; nf < 8; nf++)
#pragma unroll
        for (int j = 0; j < 4; j++) c[nf][j] = 0.f;

#pragma unroll
    for (int ks = 0; ks < 8; ks++) {
        int kb = ks * 16 + q * 2;
        float2 xa0 = *(const float2*)&x[nl0 + kb];
        float2 xa1 = *(const float2*)&x[nl1 + kb];
        float2 xa2 = *(const float2*)&x[nl0 + kb + 8];
        float2 xa3 = *(const float2*)&x[nl1 + kb + 8];
        __half2 h0 = __floats2half2_rn(xa0.x, xa0.y);
        __half2 h1 = __floats2half2_rn(xa1.x, xa1.y);
        __half2 h2 = __floats2half2_rn(xa2.x, xa2.y);
        __half2 h3 = __floats2half2_rn(xa3.x, xa3.y);
        unsigned a0 = *(unsigned*)&h0, a1 = *(unsigned*)&h1;
        unsigned a2 = *(unsigned*)&h2, a3 = *(unsigned*)&h3;
#pragma unroll
        for (int nf = 0; nf < 8; nf++) {
            int nfg = nhalf * 8 + nf;
            uint2 b = *(const uint2*)&g_w1f[((ks * 16 + nfg) * 32 + t) * 2];
            asm volatile(
                "mma.sync.aligned.m16n8k16.row.col.f32.f16.f16.f32 "
                "{%0,%1,%2,%3}, {%4,%5,%6,%7}, {%8,%9}, {%0,%1,%2,%3};\n"
                : "+f"(c[nf][0]), "+f"(c[nf][1]), "+f"(c[nf][2]), "+f"(c[nf][3])
                : "r"(a0), "r"(a1), "r"(a2), "r"(a3), "r"(b.x), "r"(b.y));
        }
    }

    float ps0 = 0.f, pd0 = 0.f, ps1 = 0.f, pd1 = 0.f;
#pragma unroll
    for (int nf = 0; nf < 8; nf++) {
        int col = nhalf * 64 + nf * 8 + q * 2;
        float as0 = att_s[col], as1 = att_s[col + 1];
        float ad0 = att_d[col], ad1 = att_d[col + 1];
        ps0 += c[nf][0] * as0 + c[nf][1] * as1;
        pd0 += c[nf][0] * ad0 + c[nf][1] * ad1;
        ps1 += c[nf][2] * as0 + c[nf][3] * as1;
        pd1 += c[nf][2] * ad0 + c[nf][3] * ad1;
        int pidx = nhalf * 32 + nf * 4 + q;
        if (node0 < n) g_xw1h[node0 * 64 + pidx] = __floats2half2_rn(c[nf][0], c[nf][1]);
        if (node1 < n) g_xw1h[node1 * 64 + pidx] = __floats2half2_rn(c[nf][2], c[nf][3]);
    }
#pragma unroll
    for (int o = 1; o <= 2; o <<= 1) {
        ps0 += __shfl_xor_sync(0xffffffffu, ps0, o);
        pd0 += __shfl_xor_sync(0xffffffffu, pd0, o);
        ps1 += __shfl_xor_sync(0xffffffffu, ps1, o);
        pd1 += __shfl_xor_sync(0xffffffffu, pd1, o);
    }
    if (q == 0) {
        if (node0 < n) { g_asrc1[node0 * 2 + nhalf] = ps0; g_adst1[node0 * 2 + nhalf] = pd0; }
        if (node1 < n) { g_asrc1[node1 * 2 + nhalf] = ps1; g_adst1[node1 * 2 + nhalf] = pd1; }
    }
}

// ------- layer-1 fused softmax+aggregate: warp/dst, 16-edge pipelined chunks -
// (R12-proven inner loop: fp32 FFMA accumulation, MLP-16 LDG batching)
__global__ void k_edge1(const float* __restrict__ b1, int n) {
    int gt = blockIdx.x * blockDim.x + threadIdx.x;
    int d  = gt >> 5;
    if (d >= n) return;
    int lane = gt & 31, h = lane >> 4, sub = lane & 15;
    int beg = (int)g_off[d], end = (int)g_off[d + 1];
    float adh = g_adst1[d * 2 + h];
    float4 acc = make_float4(0.f, 0.f, 0.f, 0.f);
    float s = 0.f;
    int base = beg;
    int msrc = 0; float ex = 0.f;
    {
        int i0 = base + sub;
        if (i0 < end) {
            msrc = g_adj[i0];
            ex = __expf(lrelu(g_asrc1[msrc * 2 + h] + adh));
        }
    }
    while (base < end) {
        int nbase = base + 16;
        int nsrc = 0; float nex = 0.f;
        if (nbase < end) {              // software-pipeline next chunk's dep chain
            int i1 = nbase + sub;
            if (i1 < end) {
                nsrc = g_adj[i1];
                nex = __expf(lrelu(g_asrc1[nsrc * 2 + h] + adh));
            }
        }
        s += ex;
        int cnt = min(16, end - base);
#pragma unroll 8
        for (int j = 0; j < cnt; j++) {
            int   src  = __shfl_sync(0xffffffffu, msrc, j);
            float coef = __shfl_sync(0xffffffffu, ex, j + (h << 4));
            uint2 p = *(const uint2*)&g_xw1h[src * 64 + lane * 2];
            float2 v01 = __half22float2(*(__half2*)&p.x);
            float2 v23 = __half22float2(*(__half2*)&p.y);
            acc.x += v01.x * coef; acc.y += v01.y * coef;
            acc.z += v23.x * coef; acc.w += v23.y * coef;
        }
        msrc = nsrc; ex = nex; base = nbase;
    }
#pragma unroll
    for (int o = 8; o >= 1; o >>= 1)    // per-half sums: lanes<16 -> s0, >=16 -> s1
        s += __shfl_xor_sync(0xffffffffu, s, o);
    float r = 1.f / (s + 1e-16f);
    float4 bb = *(const float4*)&b1[lane * 4];
    __half2 o01 = __floats2half2_rn(acc.x * r + bb.x, acc.y * r + bb.y);
    __half2 o23 = __floats2half2_rn(acc.z * r + bb.z, acc.w * r + bb.w);
    uint2 pk = make_uint2(*(unsigned*)&o01, *(unsigned*)&o23);
    *(uint2*)&g_out1h[d * 64 + lane * 2] = pk;
}

// ----- layer-2 GEMM (16 nodes/block, fp16 in + relu fused) + att2 dots -------
__global__ __launch_bounds__(256) void k_gemm2(const float* __restrict__ att_s,
                                               const float* __restrict__ att_d, int n) {
    __shared__ float xs[16 * 132];
    int t  = threadIdx.x;            // 256 threads = 16 nodes x 16 outs
    int nb = blockIdx.x * 16;
#pragma unroll
    for (int i = 0; i < 4; i++) {
        int idx  = t + i * 256;      // 0..1023 over 16 nodes x 64 half2
        int node = idx >> 6, kh = idx & 63;
        float2 v = make_float2(0.f, 0.f);
        if (nb + node < n) {
            __half2 hv = g_out1h[(nb + node) * 64 + kh];
            v = __half22float2(hv);
        }
        xs[node * 132 + kh * 2 + 0] = fmaxf(v.x, 0.f);   // relu
        xs[node * 132 + kh * 2 + 1] = fmaxf(v.y, 0.f);
    }
    __syncthreads();
    int ni = t >> 4;
    int o  = t & 15;
    float a0 = 0.f, a1 = 0.f, a2 = 0.f, a3 = 0.f;
#pragma unroll
    for (int k4 = 0; k4 < D1 / 4; k4 += 4) {
#pragma unroll
        for (int u = 0; u < 4; u++) {
            float4 w  = g_w2t4[(k4 + u) * NC + o];
            float4 xv = *(const float4*)&xs[ni * 132 + (k4 + u) * 4];
            float p = xv.x * w.x + xv.y * w.y + xv.z * w.z + xv.w * w.w;
            if (u == 0) a0 += p; else if (u == 1) a1 += p; else if (u == 2) a2 += p; else a3 += p;
        }
    }
    float acc = (a0 + a1) + (a2 + a3);
    int node = nb + ni;
    if (node < n) g_xw2h[node * NC + o] = __float2half(acc);
    float ps = acc * att_s[o];
    float pd = acc * att_d[o];
#pragma unroll
    for (int j = 8; j >= 1; j >>= 1) {
        ps += __shfl_xor_sync(0xffffffffu, ps, j);
        pd += __shfl_xor_sync(0xffffffffu, pd, j);
    }
    if (o == 0 && node < n) { g_asrc2[node] = ps; g_adst2[node] = pd; }
}

// ---------------- layer-2 fused softmax+aggregate (warp per dst) -------------
__global__ void k_edge2(const float* __restrict__ b2, float* __restrict__ out, int n) {
    int gt = blockIdx.x * blockDim.x + threadIdx.x;
    int d  = gt >> 5;
    if (d >= n) return;
    int lane = gt & 31;
    int beg = (int)g_off[d], end = (int)g_off[d + 1];
    float add = g_adst2[d];
    int half = lane >> 4;
    int c    = lane & 15;
    float acc = 0.f, s = 0.f;
    for (int base = beg; base < end; base += 32) {
        int myi = base + lane;
        float ev = 0.f;
        int msrc = 0;
        if (myi < end) {
            msrc = g_adj[myi];
            ev = __expf(lrelu(g_asrc2[msrc] + add));
        }
        s += ev;
        int cnt = min(32, end - base);
#pragma unroll 4
        for (int j = 0; j < cnt; j += 2) {
            int jj = j + half;                  // lanes 0-15 edge j, 16-31 edge j+1
            int   src = __shfl_sync(0xffffffffu, msrc, jj & 31);
            float e   = __shfl_sync(0xffffffffu, ev, jj & 31);
            if (jj < cnt)
                acc += __half2float(g_xw2h[src * NC + c]) * e;
        }
    }
#pragma unroll
    for (int o = 16; o >= 1; o >>= 1)
        s += __shfl_xor_sync(0xffffffffu, s, o);
    acc += __shfl_xor_sync(0xffffffffu, acc, 16);
    if (half == 0) {
        float r = 1.f / (s + 1e-16f);
        out[d * NC + c] = acc * r + b2[c];
    }
}

// ---------------- launcher ----------------------------------------------------
extern "C" void kernel_launch(void* const* d_in, const int* in_sizes, int n_in,
                              void* d_out, int out_size) {
    const float* x   = (const float*)d_in[0];
    const int*   ei  = (const int*)d_in[1];      // int32
    const float* w1  = (const float*)d_in[2];
    const float* as1 = (const float*)d_in[3];
    const float* ad1 = (const float*)d_in[4];
    const float* b1  = (const float*)d_in[5];
    const float* w2  = (const float*)d_in[6];
    const float* as2 = (const float*)d_in[7];
    const float* ad2 = (const float*)d_in[8];
    const float* b2  = (const float*)d_in[9];
    float* out = (float*)d_out;

    int n  = in_sizes[0] / FIN;     // 50000
    int E  = in_sizes[1] / 2;       // 1600000
    int ET = E + n;                 // 1650000
    int g1 = (n + 63) / 64;         // gemm1 blocks in K2

    // K1: prep + hist + last-block scan
    k_build<<<(ET + 1023) / 1024, 1024>>>(w1, w2, ei, E, ET, n);
    // K2: gemm1 (blocks [0,g1)) + scatter (rest)
    k_g1scatter<<<g1 + (ET + 255) / 256, 256>>>(x, ei, as1, ad1, n, E, ET, g1);
    // K3: layer-1 softmax+aggregate
    k_edge1<<<(n * 32 + 255) / 256, 256>>>(b1, n);
    // K4 (profiled): layer-2 GEMM + att2 dots
    k_gemm2<<<(n + 15) / 16, 256>>>(as2, ad2, n);
    // K5: layer-2 softmax+aggregate
    k_edge2<<<(n * 32 + 255) / 256, 256>>>(b2, out, n);
}

// round 15
// speedup vs baseline: 1.0411x; 1.0064x over previous
#include <cuda_runtime.h>
#include <cuda_fp16.h>

// Problem constants (fixed shapes for this problem)
#define Nn    50000
#define FIN   128
#define D1    128           // H1*C1
#define NC    16
#define EMAX  1600000
#define ETMAX (EMAX + Nn)

// ---------------- scratch (device globals; no allocation allowed) ------------
__device__ unsigned   g_w1f[8 * 16 * 32 * 2]; // w1 in mma B-fragment order (half2 as u32)
__device__ float4     g_w2t4[(D1 / 4) * NC];
__device__ __half2    g_xw1h[Nn * 64];        // fp16 gather payload (layer 1)
__device__ __half2    g_out1h[Nn * 64];       // fp16 layer-1 output
__device__ float      g_asrc1[Nn * 2];
__device__ float      g_adst1[Nn * 2];
__device__ __half     g_xw2h[Nn * NC];        // fp16 gather payload (layer 2)
__device__ float      g_asrc2[Nn];
__device__ float      g_adst2[Nn];
__device__ unsigned   g_cnt[Nn];              // invariant: zero at kernel_launch entry
__device__ unsigned   g_off[Nn + 1];
__device__ unsigned   g_cur[Nn];
__device__ int        g_adj[ETMAX];           // CSR by dst: src node ids
__device__ unsigned   g_tick;                 // invariant: zero at kernel_launch entry

__device__ __forceinline__ float lrelu(float a) { return a > 0.f ? a : 0.2f * a; }

// ------ K1: prep (weight repack) + int4 CSR histogram + last-block scan ------
__global__ __launch_bounds__(1024) void k_build(const float* __restrict__ w1,
                                                const float* __restrict__ w2,
                                                const int* __restrict__ ei,
                                                int E, int ET, int n) {
    int gi = blockIdx.x * 1024 + threadIdx.x;
    // prep: w1 -> mma B-fragment order
    if (gi < 8 * 16 * 32 * 2) {
        int reg  = gi & 1;
        int lane = (gi >> 1) & 31;
        int nfg  = (gi >> 6) & 15;
        int ks   = gi >> 10;
        int nn = nfg * 8 + (lane >> 2);
        int k  = ks * 16 + (lane & 3) * 2 + reg * 8;
        __half2 h = __floats2half2_rn(w1[nn * FIN + k], w1[nn * FIN + k + 1]);
        g_w1f[gi] = *(unsigned*)&h;
    }
    if (gi < NC * D1) {
        int o = gi / D1, k = gi % D1;
        ((float*)g_w2t4)[((k >> 2) * NC + o) * 4 + (k & 3)] = w2[gi];
    }
    // int4 histogram: 4 edges per thread (E % 4 == 0, no straddle)
    {
        int base = gi * 4;
        if (base < E) {
            int4 d4 = *(const int4*)&ei[E + base];
            atomicAdd(&g_cnt[d4.x], 1u);
            atomicAdd(&g_cnt[d4.y], 1u);
            atomicAdd(&g_cnt[d4.z], 1u);
            atomicAdd(&g_cnt[d4.w], 1u);
        } else {
#pragma unroll
            for (int rr = 0; rr < 4; rr++) {
                int e = base + rr;
                if (e < ET) atomicAdd(&g_cnt[e - E], 1u);
            }
        }
    }
    // ticket: last block performs the scan
    __threadfence();
    __syncthreads();
    __shared__ unsigned s_last;
    if (threadIdx.x == 0)
        s_last = (atomicAdd(&g_tick, 1u) == gridDim.x - 1) ? 1u : 0u;
    __syncthreads();
    if (!s_last) return;

    // 1024-thread scan over g_cnt (+ re-zero), producing g_off / g_cur
    __shared__ unsigned ssum[1024];
    int t = threadIdx.x;
    int chunk = (n + 1023) >> 10;
    int b = t * chunk;
    int e = min(b + chunk, n);
    unsigned sum = 0;
    for (int i = b; i < e; i++) sum += g_cnt[i];
    ssum[t] = sum;
    __syncthreads();
    for (int o = 1; o < 1024; o <<= 1) {
        unsigned v = (t >= o) ? ssum[t - o] : 0u;
        __syncthreads();
        ssum[t] += v;
        __syncthreads();
    }
    unsigned run = (t == 0) ? 0u : ssum[t - 1];
    for (int i = b; i < e; i++) {
        unsigned c = g_cnt[i];
        g_cnt[i] = 0u;                            // restore invariant
        g_off[i] = run;
        g_cur[i] = run;
        run += c;
    }
    if (t == 0) { g_off[n] = ssum[1023]; g_tick = 0u; }   // restore invariant
}

// ------ K2: gemm1 (blocks [0,g1)) + int4 CSR scatter (blocks [g1,...)) -------
// gemm1: 64 nodes/block; 8 warps = 4 M-frags x 2 N-halves; N-half == head.
__global__ __launch_bounds__(256) void k_g1scatter(const float* __restrict__ x,
                                                   const int* __restrict__ ei,
                                                   const float* __restrict__ att_s,
                                                   const float* __restrict__ att_d,
                                                   int n, int E, int ET, int g1) {
    if (blockIdx.x >= g1) {
        // ---- scatter path: 4 edges per thread ----
        int base = ((blockIdx.x - g1) * 256 + threadIdx.x) * 4;
        if (base < E) {
            int4 s4 = *(const int4*)&ei[base];
            int4 d4 = *(const int4*)&ei[E + base];
            g_adj[atomicAdd(&g_cur[d4.x], 1u)] = s4.x;
            g_adj[atomicAdd(&g_cur[d4.y], 1u)] = s4.y;
            g_adj[atomicAdd(&g_cur[d4.z], 1u)] = s4.z;
            g_adj[atomicAdd(&g_cur[d4.w], 1u)] = s4.w;
        } else {
#pragma unroll
            for (int rr = 0; rr < 4; rr++) {
                int e = base + rr;
                if (e < ET) {
                    int sl = e - E;
                    g_adj[atomicAdd(&g_cur[sl], 1u)] = sl;
                }
            }
        }
        return;
    }
    // ---- gemm1 path ----
    int tid = threadIdx.x;
    int w = tid >> 5, t = tid & 31;
    int mfrag = w >> 1, nhalf = w & 1;
    int r = t >> 2, q = t & 3;
    int node0 = blockIdx.x * 64 + mfrag * 16 + r;
    int node1 = node0 + 8;
    int nl0 = min(node0, n - 1) * FIN;
    int nl1 = min(node1, n - 1) * FIN;

    float c[8][4];
#pragma unroll
    for (int nf = 0; nf < 8; nf++)
#pragma unroll
        for (int j = 0; j < 4; j++) c[nf][j] = 0.f;

#pragma unroll
    for (int ks = 0; ks < 8; ks++) {
        int kb = ks * 16 + q * 2;
        float2 xa0 = *(const float2*)&x[nl0 + kb];
        float2 xa1 = *(const float2*)&x[nl1 + kb];
        float2 xa2 = *(const float2*)&x[nl0 + kb + 8];
        float2 xa3 = *(const float2*)&x[nl1 + kb + 8];
        __half2 h0 = __floats2half2_rn(xa0.x, xa0.y);
        __half2 h1 = __floats2half2_rn(xa1.x, xa1.y);
        __half2 h2 = __floats2half2_rn(xa2.x, xa2.y);
        __half2 h3 = __floats2half2_rn(xa3.x, xa3.y);
        unsigned a0 = *(unsigned*)&h0, a1 = *(unsigned*)&h1;
        unsigned a2 = *(unsigned*)&h2, a3 = *(unsigned*)&h3;
#pragma unroll
        for (int nf = 0; nf < 8; nf++) {
            int nfg = nhalf * 8 + nf;
            uint2 b = *(const uint2*)&g_w1f[((ks * 16 + nfg) * 32 + t) * 2];
            asm volatile(
                "mma.sync.aligned.m16n8k16.row.col.f32.f16.f16.f32 "
                "{%0,%1,%2,%3}, {%4,%5,%6,%7}, {%8,%9}, {%0,%1,%2,%3};\n"
                : "+f"(c[nf][0]), "+f"(c[nf][1]), "+f"(c[nf][2]), "+f"(c[nf][3])
                : "r"(a0), "r"(a1), "r"(a2), "r"(a3), "r"(b.x), "r"(b.y));
        }
    }

    float ps0 = 0.f, pd0 = 0.f, ps1 = 0.f, pd1 = 0.f;
#pragma unroll
    for (int nf = 0; nf < 8; nf++) {
        int col = nhalf * 64 + nf * 8 + q * 2;
        float as0 = att_s[col], as1 = att_s[col + 1];
        float ad0 = att_d[col], ad1 = att_d[col + 1];
        ps0 += c[nf][0] * as0 + c[nf][1] * as1;
        pd0 += c[nf][0] * ad0 + c[nf][1] * ad1;
        ps1 += c[nf][2] * as0 + c[nf][3] * as1;
        pd1 += c[nf][2] * ad0 + c[nf][3] * ad1;
        int pidx = nhalf * 32 + nf * 4 + q;
        if (node0 < n) g_xw1h[node0 * 64 + pidx] = __floats2half2_rn(c[nf][0], c[nf][1]);
        if (node1 < n) g_xw1h[node1 * 64 + pidx] = __floats2half2_rn(c[nf][2], c[nf][3]);
    }
#pragma unroll
    for (int o = 1; o <= 2; o <<= 1) {
        ps0 += __shfl_xor_sync(0xffffffffu, ps0, o);
        pd0 += __shfl_xor_sync(0xffffffffu, pd0, o);
        ps1 += __shfl_xor_sync(0xffffffffu, ps1, o);
        pd1 += __shfl_xor_sync(0xffffffffu, pd1, o);
    }
    if (q == 0) {
        if (node0 < n) { g_asrc1[node0 * 2 + nhalf] = ps0; g_adst1[node0 * 2 + nhalf] = pd0; }
        if (node1 < n) { g_asrc1[node1 * 2 + nhalf] = ps1; g_adst1[node1 * 2 + nhalf] = pd1; }
    }
}

// ------- layer-1 fused softmax+aggregate: warp/dst, 16-edge pipelined chunks -
// (R12-proven inner loop: fp32 FFMA accumulation, MLP-16 LDG batching)
__global__ void k_edge1(const float* __restrict__ b1, int n) {
    int gt = blockIdx.x * blockDim.x + threadIdx.x;
    int d  = gt >> 5;
    if (d >= n) return;
    int lane = gt & 31, h = lane >> 4, sub = lane & 15;
    int beg = (int)g_off[d], end = (int)g_off[d + 1];
    float adh = g_adst1[d * 2 + h];
    float4 acc = make_float4(0.f, 0.f, 0.f, 0.f);
    float s = 0.f;
    int base = beg;
    int msrc = 0; float ex = 0.f;
    {
        int i0 = base + sub;
        if (i0 < end) {
            msrc = g_adj[i0];
            ex = __expf(lrelu(g_asrc1[msrc * 2 + h] + adh));
        }
    }
    while (base < end) {
        int nbase = base + 16;
        int nsrc = 0; float nex = 0.f;
        if (nbase < end) {              // software-pipeline next chunk's dep chain
            int i1 = nbase + sub;
            if (i1 < end) {
                nsrc = g_adj[i1];
                nex = __expf(lrelu(g_asrc1[nsrc * 2 + h] + adh));
            }
        }
        s += ex;
        int cnt = min(16, end - base);
#pragma unroll 8
        for (int j = 0; j < cnt; j++) {
            int   src  = __shfl_sync(0xffffffffu, msrc, j);
            float coef = __shfl_sync(0xffffffffu, ex, j + (h << 4));
            uint2 p = *(const uint2*)&g_xw1h[src * 64 + lane * 2];
            float2 v01 = __half22float2(*(__half2*)&p.x);
            float2 v23 = __half22float2(*(__half2*)&p.y);
            acc.x += v01.x * coef; acc.y += v01.y * coef;
            acc.z += v23.x * coef; acc.w += v23.y * coef;
        }
        msrc = nsrc; ex = nex; base = nbase;
    }
#pragma unroll
    for (int o = 8; o >= 1; o >>= 1)    // per-half sums: lanes<16 -> s0, >=16 -> s1
        s += __shfl_xor_sync(0xffffffffu, s, o);
    float r = 1.f / (s + 1e-16f);
    float4 bb = *(const float4*)&b1[lane * 4];
    __half2 o01 = __floats2half2_rn(acc.x * r + bb.x, acc.y * r + bb.y);
    __half2 o23 = __floats2half2_rn(acc.z * r + bb.z, acc.w * r + bb.w);
    uint2 pk = make_uint2(*(unsigned*)&o01, *(unsigned*)&o23);
    *(uint2*)&g_out1h[d * 64 + lane * 2] = pk;
}

// ----- layer-2 GEMM (16 nodes/block, w2 staged in smem) + att2 dots ----------
__global__ __launch_bounds__(256) void k_gemm2(const float* __restrict__ att_s,
                                               const float* __restrict__ att_d, int n) {
    __shared__ float  xs[16 * 132];
    __shared__ float4 ws[(D1 / 4) * NC];     // 8 KB staged w2
    int t  = threadIdx.x;            // 256 threads = 16 nodes x 16 outs
    int nb = blockIdx.x * 16;
#pragma unroll
    for (int i = 0; i < 2; i++)      // 512 float4 total
        ws[t + i * 256] = g_w2t4[t + i * 256];
#pragma unroll
    for (int i = 0; i < 4; i++) {
        int idx  = t + i * 256;      // 0..1023 over 16 nodes x 64 half2
        int node = idx >> 6, kh = idx & 63;
        float2 v = make_float2(0.f, 0.f);
        if (nb + node < n) {
            __half2 hv = g_out1h[(nb + node) * 64 + kh];
            v = __half22float2(hv);
        }
        xs[node * 132 + kh * 2 + 0] = fmaxf(v.x, 0.f);   // relu
        xs[node * 132 + kh * 2 + 1] = fmaxf(v.y, 0.f);
    }
    __syncthreads();
    int ni = t >> 4;
    int o  = t & 15;
    float a0 = 0.f, a1 = 0.f, a2 = 0.f, a3 = 0.f;
#pragma unroll
    for (int k4 = 0; k4 < D1 / 4; k4 += 4) {
#pragma unroll
        for (int u = 0; u < 4; u++) {
            float4 w  = ws[(k4 + u) * NC + o];
            float4 xv = *(const float4*)&xs[ni * 132 + (k4 + u) * 4];
            float p = xv.x * w.x + xv.y * w.y + xv.z * w.z + xv.w * w.w;
            if (u == 0) a0 += p; else if (u == 1) a1 += p; else if (u == 2) a2 += p; else a3 += p;
        }
    }
    float acc = (a0 + a1) + (a2 + a3);
    int node = nb + ni;
    if (node < n) g_xw2h[node * NC + o] = __float2half(acc);
    float ps = acc * att_s[o];
    float pd = acc * att_d[o];
#pragma unroll
    for (int j = 8; j >= 1; j >>= 1) {
        ps += __shfl_xor_sync(0xffffffffu, ps, j);
        pd += __shfl_xor_sync(0xffffffffu, pd, j);
    }
    if (o == 0 && node < n) { g_asrc2[node] = ps; g_adst2[node] = pd; }
}

// ---------------- layer-2 fused softmax+aggregate (warp per dst) -------------
__global__ void k_edge2(const float* __restrict__ b2, float* __restrict__ out, int n) {
    int gt = blockIdx.x * blockDim.x + threadIdx.x;
    int d  = gt >> 5;
    if (d >= n) return;
    int lane = gt & 31;
    int beg = (int)g_off[d], end = (int)g_off[d + 1];
    float add = g_adst2[d];
    int half = lane >> 4;
    int c    = lane & 15;
    float acc = 0.f, s = 0.f;
    for (int base = beg; base < end; base += 32) {
        int myi = base + lane;
        float ev = 0.f;
        int msrc = 0;
        if (myi < end) {
            msrc = g_adj[myi];
            ev = __expf(lrelu(g_asrc2[msrc] + add));
        }
        s += ev;
        int cnt = min(32, end - base);
#pragma unroll 4
        for (int j = 0; j < cnt; j += 2) {
            int jj = j + half;                  // lanes 0-15 edge j, 16-31 edge j+1
            int   src = __shfl_sync(0xffffffffu, msrc, jj & 31);
            float e   = __shfl_sync(0xffffffffu, ev, jj & 31);
            if (jj < cnt)
                acc += __half2float(g_xw2h[src * NC + c]) * e;
        }
    }
#pragma unroll
    for (int o = 16; o >= 1; o >>= 1)
        s += __shfl_xor_sync(0xffffffffu, s, o);
    acc += __shfl_xor_sync(0xffffffffu, acc, 16);
    if (half == 0) {
        float r = 1.f / (s + 1e-16f);
        out[d * NC + c] = acc * r + b2[c];
    }
}

// ---------------- launcher ----------------------------------------------------
extern "C" void kernel_launch(void* const* d_in, const int* in_sizes, int n_in,
                              void* d_out, int out_size) {
    const float* x   = (const float*)d_in[0];
    const int*   ei  = (const int*)d_in[1];      // int32
    const float* w1  = (const float*)d_in[2];
    const float* as1 = (const float*)d_in[3];
    const float* ad1 = (const float*)d_in[4];
    const float* b1  = (const float*)d_in[5];
    const float* w2  = (const float*)d_in[6];
    const float* as2 = (const float*)d_in[7];
    const float* ad2 = (const float*)d_in[8];
    const float* b2  = (const float*)d_in[9];
    float* out = (float*)d_out;

    int n  = in_sizes[0] / FIN;     // 50000
    int E  = in_sizes[1] / 2;       // 1600000
    int ET = E + n;                 // 1650000
    int q4 = (ET + 3) / 4;          // int4-vectorized edge threads
    int g1 = (n + 63) / 64;         // gemm1 blocks in K2

    // K1: prep + int4 hist + last-block scan
    k_build<<<(q4 + 1023) / 1024, 1024>>>(w1, w2, ei, E, ET, n);
    // K2: gemm1 (blocks [0,g1)) + int4 scatter (rest)
    k_g1scatter<<<g1 + (q4 + 255) / 256, 256>>>(x, ei, as1, ad1, n, E, ET, g1);
    // K3: layer-1 softmax+aggregate
    k_edge1<<<(n * 32 + 255) / 256, 256>>>(b1, n);
    // K4 (profiled): layer-2 GEMM (smem w2) + att2 dots
    k_gemm2<<<(n + 15) / 16, 256>>>(as2, ad2, n);
    // K5: layer-2 softmax+aggregate
    k_edge2<<<(n * 32 + 255) / 256, 256>>>(b2, out, n);
}

// round 16
// speedup vs baseline: 1.1069x; 1.0632x over previous
#include <cuda_runtime.h>
#include <cuda_fp16.h>

// Problem constants (fixed shapes for this problem)
#define Nn    50000
#define FIN   128
#define D1    128           // H1*C1
#define NC    16
#define EMAX  1600000
#define ETMAX (EMAX + Nn)

// ---------------- scratch (device globals; no allocation allowed) ------------
__device__ unsigned   g_w1f[8 * 16 * 32 * 2]; // w1 in mma B-fragment order (half2 as u32)
__device__ unsigned   g_w2f[8 * 2 * 32 * 2];  // w2 in mma B-fragment order
__device__ __half2    g_xw1h[Nn * 64];        // fp16 gather payload (layer 1)
__device__ __half2    g_out1h[Nn * 64];       // fp16 layer-1 output
__device__ float      g_asrc1[Nn * 2];
__device__ float      g_adst1[Nn * 2];
__device__ __half     g_xw2h[Nn * NC];        // fp16 gather payload (layer 2)
__device__ float      g_asrc2[Nn];
__device__ float      g_adst2[Nn];
__device__ unsigned   g_cnt[Nn];              // invariant: zero at kernel_launch entry
__device__ unsigned   g_off[Nn + 1];
__device__ unsigned   g_cur[Nn];
__device__ int        g_adj[ETMAX];           // CSR by dst: src node ids
__device__ unsigned   g_tick;                 // invariant: zero at kernel_launch entry

__device__ __forceinline__ float lrelu(float a) { return a > 0.f ? a : 0.2f * a; }

// ------ K1: prep (weight repacks) + int4 CSR histogram + last-block scan -----
__global__ __launch_bounds__(1024) void k_build(const float* __restrict__ w1,
                                                const float* __restrict__ w2,
                                                const int* __restrict__ ei,
                                                int E, int ET, int n) {
    int gi = blockIdx.x * 1024 + threadIdx.x;
    // prep: w1 -> mma B-fragment order
    if (gi < 8 * 16 * 32 * 2) {
        int reg  = gi & 1;
        int lane = (gi >> 1) & 31;
        int nfg  = (gi >> 6) & 15;
        int ks   = gi >> 10;
        int nn = nfg * 8 + (lane >> 2);
        int k  = ks * 16 + (lane & 3) * 2 + reg * 8;
        __half2 h = __floats2half2_rn(w1[nn * FIN + k], w1[nn * FIN + k + 1]);
        g_w1f[gi] = *(unsigned*)&h;
    }
    // prep: w2 -> mma B-fragment order (2 n-frags x 8 k-steps)
    if (gi < 8 * 2 * 32 * 2) {
        int reg  = gi & 1;
        int lane = (gi >> 1) & 31;
        int nf   = (gi >> 6) & 1;
        int ks   = gi >> 7;
        int nn = nf * 8 + (lane >> 2);                  // output channel 0..15
        int k  = ks * 16 + (lane & 3) * 2 + reg * 8;    // input channel
        __half2 h = __floats2half2_rn(w2[nn * D1 + k], w2[nn * D1 + k + 1]);
        g_w2f[gi] = *(unsigned*)&h;
    }
    // int4 histogram: 4 edges per thread (E % 4 == 0, no straddle)
    {
        int base = gi * 4;
        if (base < E) {
            int4 d4 = *(const int4*)&ei[E + base];
            atomicAdd(&g_cnt[d4.x], 1u);
            atomicAdd(&g_cnt[d4.y], 1u);
            atomicAdd(&g_cnt[d4.z], 1u);
            atomicAdd(&g_cnt[d4.w], 1u);
        } else {
#pragma unroll
            for (int rr = 0; rr < 4; rr++) {
                int e = base + rr;
                if (e < ET) atomicAdd(&g_cnt[e - E], 1u);
            }
        }
    }
    // ticket: last block performs the scan
    __threadfence();
    __syncthreads();
    __shared__ unsigned s_last;
    if (threadIdx.x == 0)
        s_last = (atomicAdd(&g_tick, 1u) == gridDim.x - 1) ? 1u : 0u;
    __syncthreads();
    if (!s_last) return;

    // 1024-thread scan over g_cnt (+ re-zero), producing g_off / g_cur
    __shared__ unsigned ssum[1024];
    int t = threadIdx.x;
    int chunk = (n + 1023) >> 10;
    int b = t * chunk;
    int e = min(b + chunk, n);
    unsigned sum = 0;
    for (int i = b; i < e; i++) sum += g_cnt[i];
    ssum[t] = sum;
    __syncthreads();
    for (int o = 1; o < 1024; o <<= 1) {
        unsigned v = (t >= o) ? ssum[t - o] : 0u;
        __syncthreads();
        ssum[t] += v;
        __syncthreads();
    }
    unsigned run = (t == 0) ? 0u : ssum[t - 1];
    for (int i = b; i < e; i++) {
        unsigned c = g_cnt[i];
        g_cnt[i] = 0u;                            // restore invariant
        g_off[i] = run;
        g_cur[i] = run;
        run += c;
    }
    if (t == 0) { g_off[n] = ssum[1023]; g_tick = 0u; }   // restore invariant
}

// ------ K2: gemm1 (blocks [0,g1)) + int4 CSR scatter (blocks [g1,...)) -------
// gemm1: 64 nodes/block; 8 warps = 4 M-frags x 2 N-halves; N-half == head.
__global__ __launch_bounds__(256) void k_g1scatter(const float* __restrict__ x,
                                                   const int* __restrict__ ei,
                                                   const float* __restrict__ att_s,
                                                   const float* __restrict__ att_d,
                                                   int n, int E, int ET, int g1) {
    if (blockIdx.x >= g1) {
        // ---- scatter path: 4 edges per thread ----
        int base = ((blockIdx.x - g1) * 256 + threadIdx.x) * 4;
        if (base < E) {
            int4 s4 = *(const int4*)&ei[base];
            int4 d4 = *(const int4*)&ei[E + base];
            g_adj[atomicAdd(&g_cur[d4.x], 1u)] = s4.x;
            g_adj[atomicAdd(&g_cur[d4.y], 1u)] = s4.y;
            g_adj[atomicAdd(&g_cur[d4.z], 1u)] = s4.z;
            g_adj[atomicAdd(&g_cur[d4.w], 1u)] = s4.w;
        } else {
#pragma unroll
            for (int rr = 0; rr < 4; rr++) {
                int e = base + rr;
                if (e < ET) {
                    int sl = e - E;
                    g_adj[atomicAdd(&g_cur[sl], 1u)] = sl;
                }
            }
        }
        return;
    }
    // ---- gemm1 path ----
    int tid = threadIdx.x;
    int w = tid >> 5, t = tid & 31;
    int mfrag = w >> 1, nhalf = w & 1;
    int r = t >> 2, q = t & 3;
    int node0 = blockIdx.x * 64 + mfrag * 16 + r;
    int node1 = node0 + 8;
    int nl0 = min(node0, n - 1) * FIN;
    int nl1 = min(node1, n - 1) * FIN;

    float c[8][4];
#pragma unroll
    for (int nf = 0; nf < 8; nf++)
#pragma unroll
        for (int j = 0; j < 4; j++) c[nf][j] = 0.f;

#pragma unroll
    for (int ks = 0; ks < 8; ks++) {
        int kb = ks * 16 + q * 2;
        float2 xa0 = *(const float2*)&x[nl0 + kb];
        float2 xa1 = *(const float2*)&x[nl1 + kb];
        float2 xa2 = *(const float2*)&x[nl0 + kb + 8];
        float2 xa3 = *(const float2*)&x[nl1 + kb + 8];
        __half2 h0 = __floats2half2_rn(xa0.x, xa0.y);
        __half2 h1 = __floats2half2_rn(xa1.x, xa1.y);
        __half2 h2 = __floats2half2_rn(xa2.x, xa2.y);
        __half2 h3 = __floats2half2_rn(xa3.x, xa3.y);
        unsigned a0 = *(unsigned*)&h0, a1 = *(unsigned*)&h1;
        unsigned a2 = *(unsigned*)&h2, a3 = *(unsigned*)&h3;
#pragma unroll
        for (int nf = 0; nf < 8; nf++) {
            int nfg = nhalf * 8 + nf;
            uint2 b = *(const uint2*)&g_w1f[((ks * 16 + nfg) * 32 + t) * 2];
            asm volatile(
                "mma.sync.aligned.m16n8k16.row.col.f32.f16.f16.f32 "
                "{%0,%1,%2,%3}, {%4,%5,%6,%7}, {%8,%9}, {%0,%1,%2,%3};\n"
                : "+f"(c[nf][0]), "+f"(c[nf][1]), "+f"(c[nf][2]), "+f"(c[nf][3])
                : "r"(a0), "r"(a1), "r"(a2), "r"(a3), "r"(b.x), "r"(b.y));
        }
    }

    float ps0 = 0.f, pd0 = 0.f, ps1 = 0.f, pd1 = 0.f;
#pragma unroll
    for (int nf = 0; nf < 8; nf++) {
        int col = nhalf * 64 + nf * 8 + q * 2;
        float as0 = att_s[col], as1 = att_s[col + 1];
        float ad0 = att_d[col], ad1 = att_d[col + 1];
        ps0 += c[nf][0] * as0 + c[nf][1] * as1;
        pd0 += c[nf][0] * ad0 + c[nf][1] * ad1;
        ps1 += c[nf][2] * as0 + c[nf][3] * as1;
        pd1 += c[nf][2] * ad0 + c[nf][3] * ad1;
        int pidx = nhalf * 32 + nf * 4 + q;
        if (node0 < n) g_xw1h[node0 * 64 + pidx] = __floats2half2_rn(c[nf][0], c[nf][1]);
        if (node1 < n) g_xw1h[node1 * 64 + pidx] = __floats2half2_rn(c[nf][2], c[nf][3]);
    }
#pragma unroll
    for (int o = 1; o <= 2; o <<= 1) {
        ps0 += __shfl_xor_sync(0xffffffffu, ps0, o);
        pd0 += __shfl_xor_sync(0xffffffffu, pd0, o);
        ps1 += __shfl_xor_sync(0xffffffffu, ps1, o);
        pd1 += __shfl_xor_sync(0xffffffffu, pd1, o);
    }
    if (q == 0) {
        if (node0 < n) { g_asrc1[node0 * 2 + nhalf] = ps0; g_adst1[node0 * 2 + nhalf] = pd0; }
        if (node1 < n) { g_asrc1[node1 * 2 + nhalf] = ps1; g_adst1[node1 * 2 + nhalf] = pd1; }
    }
}

// ------- layer-1 fused softmax+aggregate: warp/dst, 16-edge pipelined chunks -
// (R12-proven inner loop: fp32 FFMA accumulation, MLP-16 LDG batching)
__global__ void k_edge1(const float* __restrict__ b1, int n) {
    int gt = blockIdx.x * blockDim.x + threadIdx.x;
    int d  = gt >> 5;
    if (d >= n) return;
    int lane = gt & 31, h = lane >> 4, sub = lane & 15;
    int beg = (int)g_off[d], end = (int)g_off[d + 1];
    float adh = g_adst1[d * 2 + h];
    float4 acc = make_float4(0.f, 0.f, 0.f, 0.f);
    float s = 0.f;
    int base = beg;
    int msrc = 0; float ex = 0.f;
    {
        int i0 = base + sub;
        if (i0 < end) {
            msrc = g_adj[i0];
            ex = __expf(lrelu(g_asrc1[msrc * 2 + h] + adh));
        }
    }
    while (base < end) {
        int nbase = base + 16;
        int nsrc = 0; float nex = 0.f;
        if (nbase < end) {              // software-pipeline next chunk's dep chain
            int i1 = nbase + sub;
            if (i1 < end) {
                nsrc = g_adj[i1];
                nex = __expf(lrelu(g_asrc1[nsrc * 2 + h] + adh));
            }
        }
        s += ex;
        int cnt = min(16, end - base);
#pragma unroll 8
        for (int j = 0; j < cnt; j++) {
            int   src  = __shfl_sync(0xffffffffu, msrc, j);
            float coef = __shfl_sync(0xffffffffu, ex, j + (h << 4));
            uint2 p = *(const uint2*)&g_xw1h[src * 64 + lane * 2];
            float2 v01 = __half22float2(*(__half2*)&p.x);
            float2 v23 = __half22float2(*(__half2*)&p.y);
            acc.x += v01.x * coef; acc.y += v01.y * coef;
            acc.z += v23.x * coef; acc.w += v23.y * coef;
        }
        msrc = nsrc; ex = nex; base = nbase;
    }
#pragma unroll
    for (int o = 8; o >= 1; o >>= 1)    // per-half sums: lanes<16 -> s0, >=16 -> s1
        s += __shfl_xor_sync(0xffffffffu, s, o);
    float r = 1.f / (s + 1e-16f);
    float4 bb = *(const float4*)&b1[lane * 4];
    __half2 o01 = __floats2half2_rn(acc.x * r + bb.x, acc.y * r + bb.y);
    __half2 o23 = __floats2half2_rn(acc.z * r + bb.z, acc.w * r + bb.w);
    uint2 pk = make_uint2(*(unsigned*)&o01, *(unsigned*)&o23);
    *(uint2*)&g_out1h[d * 64 + lane * 2] = pk;
}

// ----- layer-2 GEMM via fp16 HMMA (relu on load) + att2 dots -----------------
// warp = 16 nodes (m16), 8 k-steps x 2 n-frags; 8 warps = 128 nodes/block.
__global__ __launch_bounds__(256) void k_gemm2(const float* __restrict__ att_s,
                                               const float* __restrict__ att_d, int n) {
    int tid = threadIdx.x;
    int w = tid >> 5, t = tid & 31;
    int r = t >> 2, q = t & 3;
    int node0 = (blockIdx.x * 8 + w) * 16 + r;
    int node1 = node0 + 8;
    int nl0 = min(node0, n - 1) * 64;    // half2 row base
    int nl1 = min(node1, n - 1) * 64;

    float c[2][4];
#pragma unroll
    for (int nf = 0; nf < 2; nf++)
#pragma unroll
        for (int j = 0; j < 4; j++) c[nf][j] = 0.f;

    __half2 hz = __float2half2_rn(0.f);
#pragma unroll
    for (int ks = 0; ks < 8; ks++) {
        __half2 v0 = __hmax2(g_out1h[nl0 + ks * 8 + q], hz);      // relu fused
        __half2 v1 = __hmax2(g_out1h[nl1 + ks * 8 + q], hz);
        __half2 v2 = __hmax2(g_out1h[nl0 + ks * 8 + q + 4], hz);
        __half2 v3 = __hmax2(g_out1h[nl1 + ks * 8 + q + 4], hz);
        unsigned a0 = *(unsigned*)&v0, a1 = *(unsigned*)&v1;
        unsigned a2 = *(unsigned*)&v2, a3 = *(unsigned*)&v3;
#pragma unroll
        for (int nf = 0; nf < 2; nf++) {
            uint2 b = *(const uint2*)&g_w2f[((ks * 2 + nf) * 32 + t) * 2];
            asm volatile(
                "mma.sync.aligned.m16n8k16.row.col.f32.f16.f16.f32 "
                "{%0,%1,%2,%3}, {%4,%5,%6,%7}, {%8,%9}, {%0,%1,%2,%3};\n"
                : "+f"(c[nf][0]), "+f"(c[nf][1]), "+f"(c[nf][2]), "+f"(c[nf][3])
                : "r"(a0), "r"(a1), "r"(a2), "r"(a3), "r"(b.x), "r"(b.y));
        }
    }

    // payload stores + att2 dots
    float ps0 = 0.f, pd0 = 0.f, ps1 = 0.f, pd1 = 0.f;
#pragma unroll
    for (int nf = 0; nf < 2; nf++) {
        int col = nf * 8 + q * 2;
        float as0 = att_s[col], as1 = att_s[col + 1];
        float ad0 = att_d[col], ad1 = att_d[col + 1];
        ps0 += c[nf][0] * as0 + c[nf][1] * as1;
        pd0 += c[nf][0] * ad0 + c[nf][1] * ad1;
        ps1 += c[nf][2] * as0 + c[nf][3] * as1;
        pd1 += c[nf][2] * ad0 + c[nf][3] * ad1;
        if (node0 < n) {
            __half2 hv = __floats2half2_rn(c[nf][0], c[nf][1]);
            *(__half2*)&g_xw2h[node0 * NC + col] = hv;
        }
        if (node1 < n) {
            __half2 hv = __floats2half2_rn(c[nf][2], c[nf][3]);
            *(__half2*)&g_xw2h[node1 * NC + col] = hv;
        }
    }
#pragma unroll
    for (int o = 1; o <= 2; o <<= 1) {
        ps0 += __shfl_xor_sync(0xffffffffu, ps0, o);
        pd0 += __shfl_xor_sync(0xffffffffu, pd0, o);
        ps1 += __shfl_xor_sync(0xffffffffu, ps1, o);
        pd1 += __shfl_xor_sync(0xffffffffu, pd1, o);
    }
    if (q == 0) {
        if (node0 < n) { g_asrc2[node0] = ps0; g_adst2[node0] = pd0; }
        if (node1 < n) { g_asrc2[node1] = ps1; g_adst2[node1] = pd1; }
    }
}

// ---------------- layer-2 fused softmax+aggregate (warp per dst) -------------
__global__ void k_edge2(const float* __restrict__ b2, float* __restrict__ out, int n) {
    int gt = blockIdx.x * blockDim.x + threadIdx.x;
    int d  = gt >> 5;
    if (d >= n) return;
    int lane = gt & 31;
    int beg = (int)g_off[d], end = (int)g_off[d + 1];
    float add = g_adst2[d];
    int half = lane >> 4;
    int c    = lane & 15;
    float acc = 0.f, s = 0.f;
    for (int base = beg; base < end; base += 32) {
        int myi = base + lane;
        float ev = 0.f;
        int msrc = 0;
        if (myi < end) {
            msrc = g_adj[myi];
            ev = __expf(lrelu(g_asrc2[msrc] + add));
        }
        s += ev;
        int cnt = min(32, end - base);
#pragma unroll 4
        for (int j = 0; j < cnt; j += 2) {
            int jj = j + half;                  // lanes 0-15 edge j, 16-31 edge j+1
            int   src = __shfl_sync(0xffffffffu, msrc, jj & 31);
            float e   = __shfl_sync(0xffffffffu, ev, jj & 31);
            if (jj < cnt)
                acc += __half2float(g_xw2h[src * NC + c]) * e;
        }
    }
#pragma unroll
    for (int o = 16; o >= 1; o >>= 1)
        s += __shfl_xor_sync(0xffffffffu, s, o);
    acc += __shfl_xor_sync(0xffffffffu, acc, 16);
    if (half == 0) {
        float r = 1.f / (s + 1e-16f);
        out[d * NC + c] = acc * r + b2[c];
    }
}

// ---------------- launcher ----------------------------------------------------
extern "C" void kernel_launch(void* const* d_in, const int* in_sizes, int n_in,
                              void* d_out, int out_size) {
    const float* x   = (const float*)d_in[0];
    const int*   ei  = (const int*)d_in[1];      // int32
    const float* w1  = (const float*)d_in[2];
    const float* as1 = (const float*)d_in[3];
    const float* ad1 = (const float*)d_in[4];
    const float* b1  = (const float*)d_in[5];
    const float* w2  = (const float*)d_in[6];
    const float* as2 = (const float*)d_in[7];
    const float* ad2 = (const float*)d_in[8];
    const float* b2  = (const float*)d_in[9];
    float* out = (float*)d_out;

    int n  = in_sizes[0] / FIN;     // 50000
    int E  = in_sizes[1] / 2;       // 1600000
    int ET = E + n;                 // 1650000
    int q4 = (ET + 3) / 4;          // int4-vectorized edge threads
    int g1 = (n + 63) / 64;         // gemm1 blocks in K2

    // K1: prep + int4 hist + last-block scan
    k_build<<<(q4 + 1023) / 1024, 1024>>>(w1, w2, ei, E, ET, n);
    // K2: gemm1 (blocks [0,g1)) + int4 scatter (rest)
    k_g1scatter<<<g1 + (q4 + 255) / 256, 256>>>(x, ei, as1, ad1, n, E, ET, g1);
    // K3: layer-1 softmax+aggregate
    k_edge1<<<(n * 32 + 255) / 256, 256>>>(b1, n);
    // K4 (profiled): layer-2 HMMA GEMM + att2 dots
    k_gemm2<<<(n + 127) / 128, 256>>>(as2, ad2, n);
    // K5: layer-2 softmax+aggregate
    k_edge2<<<(n * 32 + 255) / 256, 256>>>(b2, out, n);
}

// round 17
// speedup vs baseline: 1.1246x; 1.0160x over previous
#include <cuda_runtime.h>
#include <cuda_fp16.h>

// Problem constants (fixed shapes for this problem)
#define Nn    50000
#define FIN   128
#define D1    128           // H1*C1
#define NC    16
#define EMAX  1600000
#define ETMAX (EMAX + Nn)

// ---------------- scratch (device globals; no allocation allowed) ------------
__device__ unsigned   g_w1f[8 * 16 * 32 * 2]; // w1 in mma B-fragment order (half2 as u32)
__device__ unsigned   g_w2f[8 * 2 * 32 * 2];  // w2 in mma B-fragment order
__device__ __half2    g_xw1h[Nn * 64];        // fp16 gather payload (layer 1)
__device__ __half2    g_out1h[Nn * 64];       // fp16 layer-1 output
__device__ float      g_asrc1[Nn * 2];
__device__ float      g_adst1[Nn * 2];
__device__ __half     g_xw2h[Nn * NC];        // fp16 gather payload (layer 2)
__device__ float      g_asrc2[Nn];
__device__ float      g_adst2[Nn];
__device__ unsigned   g_cnt[Nn];              // invariant: zero at kernel_launch entry
__device__ unsigned   g_off[Nn + 1];
__device__ unsigned   g_cur[Nn];
__device__ int        g_adj[ETMAX];           // CSR by dst: src node ids
__device__ unsigned   g_tick;                 // invariant: zero at kernel_launch entry

__device__ __forceinline__ float lrelu(float a) { return a > 0.f ? a : 0.2f * a; }

// ------ K1: prep (weight repacks) + int4 CSR histogram + last-block scan -----
__global__ __launch_bounds__(1024) void k_build(const float* __restrict__ w1,
                                                const float* __restrict__ w2,
                                                const int* __restrict__ ei,
                                                int E, int ET, int n) {
    int gi = blockIdx.x * 1024 + threadIdx.x;
    // prep: w1 -> mma B-fragment order
    if (gi < 8 * 16 * 32 * 2) {
        int reg  = gi & 1;
        int lane = (gi >> 1) & 31;
        int nfg  = (gi >> 6) & 15;
        int ks   = gi >> 10;
        int nn = nfg * 8 + (lane >> 2);
        int k  = ks * 16 + (lane & 3) * 2 + reg * 8;
        __half2 h = __floats2half2_rn(w1[nn * FIN + k], w1[nn * FIN + k + 1]);
        g_w1f[gi] = *(unsigned*)&h;
    }
    // prep: w2 -> mma B-fragment order (2 n-frags x 8 k-steps)
    if (gi < 8 * 2 * 32 * 2) {
        int reg  = gi & 1;
        int lane = (gi >> 1) & 31;
        int nf   = (gi >> 6) & 1;
        int ks   = gi >> 7;
        int nn = nf * 8 + (lane >> 2);                  // output channel 0..15
        int k  = ks * 16 + (lane & 3) * 2 + reg * 8;    // input channel
        __half2 h = __floats2half2_rn(w2[nn * D1 + k], w2[nn * D1 + k + 1]);
        g_w2f[gi] = *(unsigned*)&h;
    }
    // int4 histogram: 4 edges per thread (E % 4 == 0, no straddle)
    {
        int base = gi * 4;
        if (base < E) {
            int4 d4 = *(const int4*)&ei[E + base];
            atomicAdd(&g_cnt[d4.x], 1u);
            atomicAdd(&g_cnt[d4.y], 1u);
            atomicAdd(&g_cnt[d4.z], 1u);
            atomicAdd(&g_cnt[d4.w], 1u);
        } else {
#pragma unroll
            for (int rr = 0; rr < 4; rr++) {
                int e = base + rr;
                if (e < ET) atomicAdd(&g_cnt[e - E], 1u);
            }
        }
    }
    // ticket: last block performs the scan
    __threadfence();
    __syncthreads();
    __shared__ unsigned s_last;
    if (threadIdx.x == 0)
        s_last = (atomicAdd(&g_tick, 1u) == gridDim.x - 1) ? 1u : 0u;
    __syncthreads();
    if (!s_last) return;

    // 1024-thread scan over g_cnt (+ re-zero), producing g_off / g_cur
    __shared__ unsigned ssum[1024];
    int t = threadIdx.x;
    int chunk = (n + 1023) >> 10;
    int b = t * chunk;
    int e = min(b + chunk, n);
    unsigned sum = 0;
    for (int i = b; i < e; i++) sum += g_cnt[i];
    ssum[t] = sum;
    __syncthreads();
    for (int o = 1; o < 1024; o <<= 1) {
        unsigned v = (t >= o) ? ssum[t - o] : 0u;
        __syncthreads();
        ssum[t] += v;
        __syncthreads();
    }
    unsigned run = (t == 0) ? 0u : ssum[t - 1];
    for (int i = b; i < e; i++) {
        unsigned c = g_cnt[i];
        g_cnt[i] = 0u;                            // restore invariant
        g_off[i] = run;
        g_cur[i] = run;
        run += c;
    }
    if (t == 0) { g_off[n] = ssum[1023]; g_tick = 0u; }   // restore invariant
}

// ------ K2: gemm1 (blocks [0,g1)) + int4 CSR scatter (blocks [g1,...)) -------
// gemm1: 64 nodes/block; 8 warps = 4 M-frags x 2 N-halves; N-half == head.
__global__ __launch_bounds__(256) void k_g1scatter(const float* __restrict__ x,
                                                   const int* __restrict__ ei,
                                                   const float* __restrict__ att_s,
                                                   const float* __restrict__ att_d,
                                                   int n, int E, int ET, int g1) {
    if (blockIdx.x >= g1) {
        // ---- scatter path: 4 edges per thread ----
        int base = ((blockIdx.x - g1) * 256 + threadIdx.x) * 4;
        if (base < E) {
            int4 s4 = *(const int4*)&ei[base];
            int4 d4 = *(const int4*)&ei[E + base];
            g_adj[atomicAdd(&g_cur[d4.x], 1u)] = s4.x;
            g_adj[atomicAdd(&g_cur[d4.y], 1u)] = s4.y;
            g_adj[atomicAdd(&g_cur[d4.z], 1u)] = s4.z;
            g_adj[atomicAdd(&g_cur[d4.w], 1u)] = s4.w;
        } else {
#pragma unroll
            for (int rr = 0; rr < 4; rr++) {
                int e = base + rr;
                if (e < ET) {
                    int sl = e - E;
                    g_adj[atomicAdd(&g_cur[sl], 1u)] = sl;
                }
            }
        }
        return;
    }
    // ---- gemm1 path ----
    int tid = threadIdx.x;
    int w = tid >> 5, t = tid & 31;
    int mfrag = w >> 1, nhalf = w & 1;
    int r = t >> 2, q = t & 3;
    int node0 = blockIdx.x * 64 + mfrag * 16 + r;
    int node1 = node0 + 8;
    int nl0 = min(node0, n - 1) * FIN;
    int nl1 = min(node1, n - 1) * FIN;

    float c[8][4];
#pragma unroll
    for (int nf = 0; nf < 8; nf++)
#pragma unroll
        for (int j = 0; j < 4; j++) c[nf][j] = 0.f;

#pragma unroll
    for (int ks = 0; ks < 8; ks++) {
        int kb = ks * 16 + q * 2;
        float2 xa0 = *(const float2*)&x[nl0 + kb];
        float2 xa1 = *(const float2*)&x[nl1 + kb];
        float2 xa2 = *(const float2*)&x[nl0 + kb + 8];
        float2 xa3 = *(const float2*)&x[nl1 + kb + 8];
        __half2 h0 = __floats2half2_rn(xa0.x, xa0.y);
        __half2 h1 = __floats2half2_rn(xa1.x, xa1.y);
        __half2 h2 = __floats2half2_rn(xa2.x, xa2.y);
        __half2 h3 = __floats2half2_rn(xa3.x, xa3.y);
        unsigned a0 = *(unsigned*)&h0, a1 = *(unsigned*)&h1;
        unsigned a2 = *(unsigned*)&h2, a3 = *(unsigned*)&h3;
#pragma unroll
        for (int nf = 0; nf < 8; nf++) {
            int nfg = nhalf * 8 + nf;
            uint2 b = *(const uint2*)&g_w1f[((ks * 16 + nfg) * 32 + t) * 2];
            asm volatile(
                "mma.sync.aligned.m16n8k16.row.col.f32.f16.f16.f32 "
                "{%0,%1,%2,%3}, {%4,%5,%6,%7}, {%8,%9}, {%0,%1,%2,%3};\n"
                : "+f"(c[nf][0]), "+f"(c[nf][1]), "+f"(c[nf][2]), "+f"(c[nf][3])
                : "r"(a0), "r"(a1), "r"(a2), "r"(a3), "r"(b.x), "r"(b.y));
        }
    }

    float ps0 = 0.f, pd0 = 0.f, ps1 = 0.f, pd1 = 0.f;
#pragma unroll
    for (int nf = 0; nf < 8; nf++) {
        int col = nhalf * 64 + nf * 8 + q * 2;
        float as0 = att_s[col], as1 = att_s[col + 1];
        float ad0 = att_d[col], ad1 = att_d[col + 1];
        ps0 += c[nf][0] * as0 + c[nf][1] * as1;
        pd0 += c[nf][0] * ad0 + c[nf][1] * ad1;
        ps1 += c[nf][2] * as0 + c[nf][3] * as1;
        pd1 += c[nf][2] * ad0 + c[nf][3] * ad1;
        int pidx = nhalf * 32 + nf * 4 + q;
        if (node0 < n) g_xw1h[node0 * 64 + pidx] = __floats2half2_rn(c[nf][0], c[nf][1]);
        if (node1 < n) g_xw1h[node1 * 64 + pidx] = __floats2half2_rn(c[nf][2], c[nf][3]);
    }
#pragma unroll
    for (int o = 1; o <= 2; o <<= 1) {
        ps0 += __shfl_xor_sync(0xffffffffu, ps0, o);
        pd0 += __shfl_xor_sync(0xffffffffu, pd0, o);
        ps1 += __shfl_xor_sync(0xffffffffu, ps1, o);
        pd1 += __shfl_xor_sync(0xffffffffu, pd1, o);
    }
    if (q == 0) {
        if (node0 < n) { g_asrc1[node0 * 2 + nhalf] = ps0; g_adst1[node0 * 2 + nhalf] = pd0; }
        if (node1 < n) { g_asrc1[node1 * 2 + nhalf] = ps1; g_adst1[node1 * 2 + nhalf] = pd1; }
    }
}

// ------- layer-1 fused softmax+aggregate: warp/dst, 16-edge pipelined chunks -
// (R12-proven inner loop: fp32 FFMA accumulation, MLP-16 LDG batching)
__global__ void k_edge1(const float* __restrict__ b1, int n) {
    int gt = blockIdx.x * blockDim.x + threadIdx.x;
    int d  = gt >> 5;
    if (d >= n) return;
    int lane = gt & 31, h = lane >> 4, sub = lane & 15;
    int beg = (int)g_off[d], end = (int)g_off[d + 1];
    float adh = g_adst1[d * 2 + h];
    float4 acc = make_float4(0.f, 0.f, 0.f, 0.f);
    float s = 0.f;
    int base = beg;
    int msrc = 0; float ex = 0.f;
    {
        int i0 = base + sub;
        if (i0 < end) {
            msrc = g_adj[i0];
            ex = __expf(lrelu(g_asrc1[msrc * 2 + h] + adh));
        }
    }
    while (base < end) {
        int nbase = base + 16;
        int nsrc = 0; float nex = 0.f;
        if (nbase < end) {              // software-pipeline next chunk's dep chain
            int i1 = nbase + sub;
            if (i1 < end) {
                nsrc = g_adj[i1];
                nex = __expf(lrelu(g_asrc1[nsrc * 2 + h] + adh));
            }
        }
        s += ex;
        int cnt = min(16, end - base);
#pragma unroll 8
        for (int j = 0; j < cnt; j++) {
            int   src  = __shfl_sync(0xffffffffu, msrc, j);
            float coef = __shfl_sync(0xffffffffu, ex, j + (h << 4));
            uint2 p = *(const uint2*)&g_xw1h[src * 64 + lane * 2];
            float2 v01 = __half22float2(*(__half2*)&p.x);
            float2 v23 = __half22float2(*(__half2*)&p.y);
            acc.x += v01.x * coef; acc.y += v01.y * coef;
            acc.z += v23.x * coef; acc.w += v23.y * coef;
        }
        msrc = nsrc; ex = nex; base = nbase;
    }
#pragma unroll
    for (int o = 8; o >= 1; o >>= 1)    // per-half sums: lanes<16 -> s0, >=16 -> s1
        s += __shfl_xor_sync(0xffffffffu, s, o);
    float r = 1.f / (s + 1e-16f);
    float4 bb = *(const float4*)&b1[lane * 4];
    __half2 o01 = __floats2half2_rn(acc.x * r + bb.x, acc.y * r + bb.y);
    __half2 o23 = __floats2half2_rn(acc.z * r + bb.z, acc.w * r + bb.w);
    uint2 pk = make_uint2(*(unsigned*)&o01, *(unsigned*)&o23);
    *(uint2*)&g_out1h[d * 64 + lane * 2] = pk;
}

// ----- layer-2 GEMM via fp16 HMMA (relu on load) + att2 dots -----------------
// warp = 16 nodes (m16), 8 k-steps x 2 n-frags; 8 warps = 128 nodes/block.
__global__ __launch_bounds__(256) void k_gemm2(const float* __restrict__ att_s,
                                               const float* __restrict__ att_d, int n) {
    int tid = threadIdx.x;
    int w = tid >> 5, t = tid & 31;
    int r = t >> 2, q = t & 3;
    int node0 = (blockIdx.x * 8 + w) * 16 + r;
    int node1 = node0 + 8;
    int nl0 = min(node0, n - 1) * 64;    // half2 row base
    int nl1 = min(node1, n - 1) * 64;

    float c[2][4];
#pragma unroll
    for (int nf = 0; nf < 2; nf++)
#pragma unroll
        for (int j = 0; j < 4; j++) c[nf][j] = 0.f;

    __half2 hz = __float2half2_rn(0.f);
#pragma unroll
    for (int ks = 0; ks < 8; ks++) {
        __half2 v0 = __hmax2(g_out1h[nl0 + ks * 8 + q], hz);      // relu fused
        __half2 v1 = __hmax2(g_out1h[nl1 + ks * 8 + q], hz);
        __half2 v2 = __hmax2(g_out1h[nl0 + ks * 8 + q + 4], hz);
        __half2 v3 = __hmax2(g_out1h[nl1 + ks * 8 + q + 4], hz);
        unsigned a0 = *(unsigned*)&v0, a1 = *(unsigned*)&v1;
        unsigned a2 = *(unsigned*)&v2, a3 = *(unsigned*)&v3;
#pragma unroll
        for (int nf = 0; nf < 2; nf++) {
            uint2 b = *(const uint2*)&g_w2f[((ks * 2 + nf) * 32 + t) * 2];
            asm volatile(
                "mma.sync.aligned.m16n8k16.row.col.f32.f16.f16.f32 "
                "{%0,%1,%2,%3}, {%4,%5,%6,%7}, {%8,%9}, {%0,%1,%2,%3};\n"
                : "+f"(c[nf][0]), "+f"(c[nf][1]), "+f"(c[nf][2]), "+f"(c[nf][3])
                : "r"(a0), "r"(a1), "r"(a2), "r"(a3), "r"(b.x), "r"(b.y));
        }
    }

    // payload stores + att2 dots
    float ps0 = 0.f, pd0 = 0.f, ps1 = 0.f, pd1 = 0.f;
#pragma unroll
    for (int nf = 0; nf < 2; nf++) {
        int col = nf * 8 + q * 2;
        float as0 = att_s[col], as1 = att_s[col + 1];
        float ad0 = att_d[col], ad1 = att_d[col + 1];
        ps0 += c[nf][0] * as0 + c[nf][1] * as1;
        pd0 += c[nf][0] * ad0 + c[nf][1] * ad1;
        ps1 += c[nf][2] * as0 + c[nf][3] * as1;
        pd1 += c[nf][2] * ad0 + c[nf][3] * ad1;
        if (node0 < n) {
            __half2 hv = __floats2half2_rn(c[nf][0], c[nf][1]);
            *(__half2*)&g_xw2h[node0 * NC + col] = hv;
        }
        if (node1 < n) {
            __half2 hv = __floats2half2_rn(c[nf][2], c[nf][3]);
            *(__half2*)&g_xw2h[node1 * NC + col] = hv;
        }
    }
#pragma unroll
    for (int o = 1; o <= 2; o <<= 1) {
        ps0 += __shfl_xor_sync(0xffffffffu, ps0, o);
        pd0 += __shfl_xor_sync(0xffffffffu, pd0, o);
        ps1 += __shfl_xor_sync(0xffffffffu, ps1, o);
        pd1 += __shfl_xor_sync(0xffffffffu, pd1, o);
    }
    if (q == 0) {
        if (node0 < n) { g_asrc2[node0] = ps0; g_adst2[node0] = pd0; }
        if (node1 < n) { g_asrc2[node1] = ps1; g_adst2[node1] = pd1; }
    }
}

// ---- layer-2 softmax+aggregate: warp/dst, 4 edges/iter, half2 loads ---------
// lane = pr*8 + c2: pr in [0,4) = edge slot, c2 in [0,8) = half2 channel pair.
__global__ void k_edge2(const float* __restrict__ b2, float* __restrict__ out, int n) {
    int gt = blockIdx.x * blockDim.x + threadIdx.x;
    int d  = gt >> 5;
    if (d >= n) return;
    int lane = gt & 31;
    int pr = lane >> 3;
    int c2 = lane & 7;
    int beg = (int)g_off[d], end = (int)g_off[d + 1];
    float add = g_adst2[d];
    float2 acc = make_float2(0.f, 0.f);
    float s = 0.f;
    for (int base = beg; base < end; base += 32) {
        int myi = base + lane;
        float ev = 0.f;
        int msrc = 0;
        if (myi < end) {
            msrc = g_adj[myi];
            ev = __expf(lrelu(g_asrc2[msrc] + add));
        }
        s += ev;
        int cnt = min(32, end - base);
#pragma unroll 8
        for (int j = 0; j < 8; j++) {
            int ej = j * 4 + pr;                // this lane's edge within chunk
            int   src = __shfl_sync(0xffffffffu, msrc, ej);
            float e   = __shfl_sync(0xffffffffu, ev, ej);
            if (ej < cnt) {
                __half2 hv = *(const __half2*)&g_xw2h[src * NC + c2 * 2];
                float2 v = __half22float2(hv);
                acc.x += v.x * e;
                acc.y += v.y * e;
            }
        }
    }
#pragma unroll
    for (int o = 16; o >= 1; o >>= 1)           // full-warp sum of exps
        s += __shfl_xor_sync(0xffffffffu, s, o);
    // fold acc across the 4 edge slots (lanes differing in bits 3,4)
    acc.x += __shfl_xor_sync(0xffffffffu, acc.x, 8);
    acc.y += __shfl_xor_sync(0xffffffffu, acc.y, 8);
    acc.x += __shfl_xor_sync(0xffffffffu, acc.x, 16);
    acc.y += __shfl_xor_sync(0xffffffffu, acc.y, 16);
    if (pr == 0) {
        float r = 1.f / (s + 1e-16f);
        float2 ov = make_float2(acc.x * r + b2[c2 * 2], acc.y * r + b2[c2 * 2 + 1]);
        *(float2*)&out[d * NC + c2 * 2] = ov;
    }
}

// ---------------- launcher ----------------------------------------------------
extern "C" void kernel_launch(void* const* d_in, const int* in_sizes, int n_in,
                              void* d_out, int out_size) {
    const float* x   = (const float*)d_in[0];
    const int*   ei  = (const int*)d_in[1];      // int32
    const float* w1  = (const float*)d_in[2];
    const float* as1 = (const float*)d_in[3];
    const float* ad1 = (const float*)d_in[4];
    const float* b1  = (const float*)d_in[5];
    const float* w2  = (const float*)d_in[6];
    const float* as2 = (const float*)d_in[7];
    const float* ad2 = (const float*)d_in[8];
    const float* b2  = (const float*)d_in[9];
    float* out = (float*)d_out;

    int n  = in_sizes[0] / FIN;     // 50000
    int E  = in_sizes[1] / 2;       // 1600000
    int ET = E + n;                 // 1650000
    int q4 = (ET + 3) / 4;          // int4-vectorized edge threads
    int g1 = (n + 63) / 64;         // gemm1 blocks in K2

    // K1: prep + int4 hist + last-block scan
    k_build<<<(q4 + 1023) / 1024, 1024>>>(w1, w2, ei, E, ET, n);
    // K2: gemm1 (blocks [0,g1)) + int4 scatter (rest)
    k_g1scatter<<<g1 + (q4 + 255) / 256, 256>>>(x, ei, as1, ad1, n, E, ET, g1);
    // K3: layer-1 softmax+aggregate
    k_edge1<<<(n * 32 + 255) / 256, 256>>>(b1, n);
    // K4 (profiled): layer-2 HMMA GEMM + att2 dots
    k_gemm2<<<(n + 127) / 128, 256>>>(as2, ad2, n);
    // K5: layer-2 softmax+aggregate (4 edges/iter, half2 loads)
    k_edge2<<<(n * 32 + 255) / 256, 256>>>(b2, out, n);
}